// round 4
// baseline (speedup 1.0000x reference)
#include <cuda_runtime.h>

#define N_P 100000
#define N_A 50000
#define E_C 1600000
#define E_W 800000
#define IND 768
#define H   128
#define HH  (128*128)

// ---------------- scratch (device globals; no allocation) ----------------
__device__ float g_hp[(size_t)N_P * H];
__device__ float g_ha[(size_t)N_A * H];
__device__ float g_zp[(size_t)N_P * H];
__device__ float g_za[(size_t)N_A * H];
__device__ float g_aggc[(size_t)N_P * H];
__device__ float g_aggw[(size_t)N_P * H];
__device__ float g_aggr[(size_t)N_A * H];
__device__ float g_Wc[2 * HH];   // 0.5*Wl[l,0]
__device__ float g_Ww[2 * HH];   // 0.5*Wl[l,1]
__device__ float g_Wrp[2 * HH];  // 0.5*(Wr[l,0]+Wr[l,1])
__device__ float g_bp[2 * H];    // 0.5*(bl[l,0]+bl[l,1])
__device__ int g_cptr[N_P + 1], g_cidx[E_C];
__device__ int g_wptr[N_P + 1], g_widx[E_W];
__device__ int g_rptr[N_A + 1], g_ridx[E_W];
__device__ int g_tmp[N_P + 1];

// ---------------- weight prep ----------------
__global__ void prep_weights(const float* __restrict__ Wl,
                             const float* __restrict__ bl,
                             const float* __restrict__ Wr) {
    int i = blockIdx.x * blockDim.x + threadIdx.x;
    if (i < HH) {
        #pragma unroll
        for (int l = 0; l < 2; l++) {
            g_Wc[l * HH + i]  = 0.5f * Wl[(l * 3 + 0) * HH + i];
            g_Ww[l * HH + i]  = 0.5f * Wl[(l * 3 + 1) * HH + i];
            g_Wrp[l * HH + i] = 0.5f * (Wr[(l * 3 + 0) * HH + i] + Wr[(l * 3 + 1) * HH + i]);
        }
    }
    if (i < H) {
        #pragma unroll
        for (int l = 0; l < 2; l++)
            g_bp[l * H + i] = 0.5f * (bl[(l * 3 + 0) * H + i] + bl[(l * 3 + 1) * H + i]);
    }
}

// ---------------- CSR build ----------------
__global__ void zero_int(int* __restrict__ p, int n) {
    int i = blockIdx.x * blockDim.x + threadIdx.x;
    if (i < n) p[i] = 0;
}

__global__ void count_k(const int* __restrict__ dst, int* __restrict__ cnt, int n) {
    int i = blockIdx.x * blockDim.x + threadIdx.x;
    if (i < n) atomicAdd(&cnt[dst[i]], 1);
}

// single-block exclusive scan over n (<= ~1M) counts -> ptr[n+1]
__global__ void scan_excl(const int* __restrict__ cnt, int* __restrict__ ptr, int n) {
    __shared__ int ss[1024];
    int tid = threadIdx.x;
    int C = (n + 1023) >> 10;
    int start = tid * C;
    int s = 0;
    for (int i = 0; i < C; i++) {
        int p = start + i;
        if (p < n) s += cnt[p];
    }
    ss[tid] = s;
    __syncthreads();
    for (int off = 1; off < 1024; off <<= 1) {
        int v = (tid >= off) ? ss[tid - off] : 0;
        __syncthreads();
        ss[tid] += v;
        __syncthreads();
    }
    int run = (tid > 0) ? ss[tid - 1] : 0;
    for (int i = 0; i < C; i++) {
        int p = start + i;
        if (p <= n) {
            ptr[p] = run;
            if (p < n) run += cnt[p];
        }
    }
}

__global__ void fill_k(const int* __restrict__ src, const int* __restrict__ dst,
                       const int* __restrict__ ptr, int* __restrict__ tmp,
                       int* __restrict__ cidx, int n) {
    int i = blockIdx.x * blockDim.x + threadIdx.x;
    if (i < n) {
        int d = dst[i];
        int p = atomicAdd(&tmp[d], 1);
        cidx[ptr[d] + p] = src[i];
    }
}

// ---------------- mean aggregation: one warp per destination node ----------------
__global__ void agg_mean(const float* __restrict__ feat, const int* __restrict__ ptr,
                         const int* __restrict__ idx, float* __restrict__ out, int n) {
    int w = (blockIdx.x * blockDim.x + threadIdx.x) >> 5;
    int lane = threadIdx.x & 31;
    if (w >= n) return;
    int beg = ptr[w], end = ptr[w + 1];
    float ax = 0.f, ay = 0.f, az = 0.f, aw = 0.f;
    int e = beg;
    for (; e + 2 <= end; e += 2) {
        int s0 = idx[e], s1 = idx[e + 1];
        float4 v0 = ((const float4*)(feat + (size_t)s0 * H))[lane];
        float4 v1 = ((const float4*)(feat + (size_t)s1 * H))[lane];
        ax += v0.x + v1.x; ay += v0.y + v1.y;
        az += v0.z + v1.z; aw += v0.w + v1.w;
    }
    if (e < end) {
        int s0 = idx[e];
        float4 v0 = ((const float4*)(feat + (size_t)s0 * H))[lane];
        ax += v0.x; ay += v0.y; az += v0.z; aw += v0.w;
    }
    int c = end - beg;
    float inv = 1.0f / (float)(c > 1 ? c : 1);
    float4 r;
    r.x = ax * inv; r.y = ay * inv; r.z = az * inv; r.w = aw * inv;
    ((float4*)(out + (size_t)w * H))[lane] = r;
}

// ---------------- fused multi-input GEMM ----------------
// out[M,128] = EPI( sum_m A_m[M,KD] @ W_m[KD,128] + bias )
// EPI 0: LayerNorm (lng,lnb) then ReLU    (projection)
// EPI 1: ReLU                             (SAGE layer 1)
// EPI 2: ReLU then += res                 (SAGE layer 2 + residual -> d_out)
template <int NMAT, int KD, int EPI>
__global__ __launch_bounds__(256) void gemm_k(
    const float* __restrict__ A0, const float* __restrict__ A1, const float* __restrict__ A2,
    const float* __restrict__ W0, const float* __restrict__ W1, const float* __restrict__ W2,
    const float* __restrict__ bias, const float* __restrict__ lng, const float* __restrict__ lnb,
    const float* __restrict__ res, float* __restrict__ out, int M) {
    __shared__ float As[NMAT][64][16];
    __shared__ float Ws[NMAT][16][128];
    const float* Aall[3] = {A0, A1, A2};
    const float* Wall[3] = {W0, W1, W2};
    int t = threadIdx.x;
    int tx = t & 31, ty = t >> 5;
    int row0 = blockIdx.x * 64;

    float acc[8][4];
    #pragma unroll
    for (int r = 0; r < 8; r++)
        #pragma unroll
        for (int i = 0; i < 4; i++) acc[r][i] = 0.f;

    #pragma unroll 1
    for (int k0 = 0; k0 < KD; k0 += 16) {
        #pragma unroll
        for (int m = 0; m < NMAT; m++) {
            const float* A = Aall[m];
            #pragma unroll
            for (int i = 0; i < 4; i++) {
                int idx = t + 256 * i;        // 64*16 elements
                int r = idx >> 4, k = idx & 15;
                int gr = row0 + r;
                As[m][r][k] = (gr < M) ? A[(size_t)gr * KD + k0 + k] : 0.f;
            }
            const float* W = Wall[m];
            #pragma unroll
            for (int i = 0; i < 8; i++) {
                int idx = t + 256 * i;        // 16*128 elements
                int k = idx >> 7, c = idx & 127;
                Ws[m][k][c] = W[(size_t)(k0 + k) * H + c];
            }
        }
        __syncthreads();
        #pragma unroll 4
        for (int kk = 0; kk < 16; kk++) {
            #pragma unroll
            for (int m = 0; m < NMAT; m++) {
                float a[8], w[4];
                #pragma unroll
                for (int r = 0; r < 8; r++) a[r] = As[m][ty + 8 * r][kk];
                #pragma unroll
                for (int i = 0; i < 4; i++) w[i] = Ws[m][kk][tx + 32 * i];
                #pragma unroll
                for (int r = 0; r < 8; r++)
                    #pragma unroll
                    for (int i = 0; i < 4; i++) acc[r][i] += a[r] * w[i];
            }
        }
        __syncthreads();
    }

    // epilogue
    float be[4], gg[4], bb[4];
    #pragma unroll
    for (int i = 0; i < 4; i++) {
        int c = tx + 32 * i;
        be[i] = bias[c];
        if (EPI == 0) { gg[i] = lng[c]; bb[i] = lnb[c]; }
    }
    #pragma unroll
    for (int r = 0; r < 8; r++) {
        int gr = row0 + ty + 8 * r;      // uniform across the warp
        if (gr >= M) continue;
        float v[4];
        #pragma unroll
        for (int i = 0; i < 4; i++) v[i] = acc[r][i] + be[i];
        if (EPI == 0) {
            float s = v[0] + v[1] + v[2] + v[3];
            #pragma unroll
            for (int o = 16; o > 0; o >>= 1) s += __shfl_xor_sync(0xffffffffu, s, o);
            float mu = s * (1.0f / 128.0f);
            float q = 0.f;
            #pragma unroll
            for (int i = 0; i < 4; i++) { float d = v[i] - mu; q += d * d; }
            #pragma unroll
            for (int o = 16; o > 0; o >>= 1) q += __shfl_xor_sync(0xffffffffu, q, o);
            float rstd = rsqrtf(q * (1.0f / 128.0f) + 1e-5f);
            #pragma unroll
            for (int i = 0; i < 4; i++) {
                float y = (v[i] - mu) * rstd * gg[i] + bb[i];
                v[i] = fmaxf(y, 0.f);
            }
        } else {
            #pragma unroll
            for (int i = 0; i < 4; i++) v[i] = fmaxf(v[i], 0.f);
            if (EPI == 2) {
                #pragma unroll
                for (int i = 0; i < 4; i++) v[i] += res[(size_t)gr * H + tx + 32 * i];
            }
        }
        #pragma unroll
        for (int i = 0; i < 4; i++) out[(size_t)gr * H + tx + 32 * i] = v[i];
    }
}

// ---------------- launch ----------------
extern "C" void kernel_launch(void* const* d_in, const int* in_sizes, int n_in,
                              void* d_out, int out_size) {
    const float* x_paper   = (const float*)d_in[0];
    const float* x_author  = (const float*)d_in[1];
    const float* pw_paper  = (const float*)d_in[2];
    const float* pb_paper  = (const float*)d_in[3];
    const float* lng_paper = (const float*)d_in[4];
    const float* lnb_paper = (const float*)d_in[5];
    const float* pw_author  = (const float*)d_in[6];
    const float* pb_author  = (const float*)d_in[7];
    const float* lng_author = (const float*)d_in[8];
    const float* lnb_author = (const float*)d_in[9];
    const float* Wl = (const float*)d_in[10];
    const float* bl = (const float*)d_in[11];
    const float* Wr = (const float*)d_in[12];
    const int* cs = (const int*)d_in[13];
    const int* cd = (const int*)d_in[14];
    const int* ws = (const int*)d_in[15];
    const int* wd = (const int*)d_in[16];
    const int* rs = (const int*)d_in[17];
    const int* rd = (const int*)d_in[18];
    float* out = (float*)d_out;

    float *hp, *ha, *zp, *za, *aggc, *aggw, *aggr, *Wc, *Ww2, *Wrp, *bp;
    int *cptr, *cidx, *wptr, *widx, *rptr, *ridx, *tmp;
    cudaGetSymbolAddress((void**)&hp, g_hp);
    cudaGetSymbolAddress((void**)&ha, g_ha);
    cudaGetSymbolAddress((void**)&zp, g_zp);
    cudaGetSymbolAddress((void**)&za, g_za);
    cudaGetSymbolAddress((void**)&aggc, g_aggc);
    cudaGetSymbolAddress((void**)&aggw, g_aggw);
    cudaGetSymbolAddress((void**)&aggr, g_aggr);
    cudaGetSymbolAddress((void**)&Wc, g_Wc);
    cudaGetSymbolAddress((void**)&Ww2, g_Ww);
    cudaGetSymbolAddress((void**)&Wrp, g_Wrp);
    cudaGetSymbolAddress((void**)&bp, g_bp);
    cudaGetSymbolAddress((void**)&cptr, g_cptr);
    cudaGetSymbolAddress((void**)&cidx, g_cidx);
    cudaGetSymbolAddress((void**)&wptr, g_wptr);
    cudaGetSymbolAddress((void**)&widx, g_widx);
    cudaGetSymbolAddress((void**)&rptr, g_rptr);
    cudaGetSymbolAddress((void**)&ridx, g_ridx);
    cudaGetSymbolAddress((void**)&tmp, g_tmp);

    prep_weights<<<(HH + 255) / 256, 256>>>(Wl, bl, Wr);

    // per-type projection: Linear -> LayerNorm -> ReLU
    gemm_k<1, IND, 0><<<(N_P + 63) / 64, 256>>>(
        x_paper, nullptr, nullptr, pw_paper, nullptr, nullptr,
        pb_paper, lng_paper, lnb_paper, nullptr, hp, N_P);
    gemm_k<1, IND, 0><<<(N_A + 63) / 64, 256>>>(
        x_author, nullptr, nullptr, pw_author, nullptr, nullptr,
        pb_author, lng_author, lnb_author, nullptr, ha, N_A);

    // CSR build (shared by both layers)
    auto build = [&](const int* s, const int* d, int nn, int ne, int* ptr, int* ci) {
        zero_int<<<(nn + 255) / 256, 256>>>(tmp, nn);
        count_k<<<(ne + 255) / 256, 256>>>(d, tmp, ne);
        scan_excl<<<1, 1024>>>(tmp, ptr, nn);
        zero_int<<<(nn + 255) / 256, 256>>>(tmp, nn);
        fill_k<<<(ne + 255) / 256, 256>>>(s, d, ptr, tmp, ci, ne);
    };
    build(cs, cd, N_P, E_C, cptr, cidx);
    build(ws, wd, N_P, E_W, wptr, widx);
    build(rs, rd, N_A, E_W, rptr, ridx);

    // ---- layer 1 ----
    agg_mean<<<(N_P + 7) / 8, 256>>>(hp, cptr, cidx, aggc, N_P);
    agg_mean<<<(N_P + 7) / 8, 256>>>(ha, wptr, widx, aggw, N_P);
    agg_mean<<<(N_A + 7) / 8, 256>>>(hp, rptr, ridx, aggr, N_A);
    gemm_k<3, H, 1><<<(N_P + 63) / 64, 256>>>(
        aggc, aggw, hp, Wc, Ww2, Wrp,
        bp, nullptr, nullptr, nullptr, zp, N_P);
    gemm_k<2, H, 1><<<(N_A + 63) / 64, 256>>>(
        aggr, ha, nullptr, Wl + 2 * HH, Wr + 2 * HH, nullptr,
        bl + 2 * H, nullptr, nullptr, nullptr, za, N_A);

    // ---- layer 2 (epilogue fuses residual, writes d_out) ----
    agg_mean<<<(N_P + 7) / 8, 256>>>(zp, cptr, cidx, aggc, N_P);
    agg_mean<<<(N_P + 7) / 8, 256>>>(za, wptr, widx, aggw, N_P);
    agg_mean<<<(N_A + 7) / 8, 256>>>(zp, rptr, ridx, aggr, N_A);
    gemm_k<3, H, 2><<<(N_P + 63) / 64, 256>>>(
        aggc, aggw, zp, Wc + HH, Ww2 + HH, Wrp + HH,
        bp + H, nullptr, nullptr, hp, out, N_P);
    gemm_k<2, H, 2><<<(N_A + 63) / 64, 256>>>(
        aggr, za, nullptr, Wl + 5 * HH, Wr + 5 * HH, nullptr,
        bl + 5 * H, nullptr, nullptr, ha, out + (size_t)N_P * H, N_A);

    (void)in_sizes; (void)n_in; (void)out_size;
}